// round 8
// baseline (speedup 1.0000x reference)
#include <cuda_runtime.h>
#include <math.h>

#define F 16
#define NVARS 500000
#define NCONSTS 250000

// ---------------- scratch (static device memory; no allocation) ----------------
__device__ float g_constraints[NCONSTS * F];   // 16 MB
__device__ float g_v2c[NCONSTS * F];           // 16 MB
__device__ float g_c2v[NVARS * F];             // 32 MB
__device__ float g_vars[NVARS * F];            // 32 MB
__device__ float g_s[NCONSTS];                 // 1 MB  (pass-1 scalar v2c)
__device__ float g_wsum[F];                    // sum over rows 16..31 of Wc
__device__ float g_w1[F];                      // sum over rows 0..15 of Wv
__device__ int   g_is64;                       // 1 if edge indices are int64

// -------- index fetch that works for both int32 and int64 edge arrays --------
__device__ __forceinline__ int fetch_idx(const void* p, int e, int is64) {
    if (is64) return (int)__ldg((const long long*)p + e);
    return __ldg((const int*)p + e);
}

// ---------------- JAX threefry2x32 noise (partitionable mode), bit-faithful ---
// element i: (b1, b2) = threefry2x32(key=(0,42), counts=(hi32(i), lo32(i))=(0,i));
// 32-bit draw = b1 ^ b2.
__device__ __forceinline__ float jax_noise(unsigned int i) {
    const unsigned int k0 = 0u, k1 = 42u;
    const unsigned int k2 = k0 ^ k1 ^ 0x1BD11BDAu;
    unsigned int x0 = 0u, x1 = i;
    x0 += k0; x1 += k1;
#define TF_RND(r) { x0 += x1; x1 = (x1 << (r)) | (x1 >> (32 - (r))); x1 ^= x0; }
    TF_RND(13) TF_RND(15) TF_RND(26) TF_RND(6)
    x0 += k1; x1 += k2 + 1u;
    TF_RND(17) TF_RND(29) TF_RND(16) TF_RND(24)
    x0 += k2; x1 += k0 + 2u;
    TF_RND(13) TF_RND(15) TF_RND(26) TF_RND(6)
    x0 += k0; x1 += k1 + 3u;
    TF_RND(17) TF_RND(29) TF_RND(16) TF_RND(24)
    x0 += k1; x1 += k2 + 4u;
    TF_RND(13) TF_RND(15) TF_RND(26) TF_RND(6)
    x0 += k2; x1 += k0 + 5u;
#undef TF_RND
    unsigned int bits = x0 ^ x1;
    // JAX uniform on [lo, hi), lo = nextafter(-1,0), hi = 1; (hi-lo) rounds to 2.0f
    float f = __uint_as_float((bits >> 9) | 0x3f800000u) - 1.0f;
    const float lo = -0.99999994f;
    float u = fmaxf(lo, fmaf(f, 2.0f, lo));
    // XLA ErfInv32 (Giles): w = -log1p(-x*x)
    float w = -log1pf(-u * u);
    float p;
    if (w < 5.0f) {
        w -= 2.5f;
        p = 2.81022636e-08f;
        p = fmaf(p, w, 3.43273939e-07f);
        p = fmaf(p, w, -3.5233877e-06f);
        p = fmaf(p, w, -4.39150654e-06f);
        p = fmaf(p, w, 0.00021858087f);
        p = fmaf(p, w, -0.00125372503f);
        p = fmaf(p, w, -0.00417768164f);
        p = fmaf(p, w, 0.246640727f);
        p = fmaf(p, w, 1.50140941f);
    } else {
        w = sqrtf(w) - 3.0f;
        p = -0.000200214257f;
        p = fmaf(p, w, 0.000100950558f);
        p = fmaf(p, w, 0.00134934322f);
        p = fmaf(p, w, -0.00367342844f);
        p = fmaf(p, w, 0.00573950773f);
        p = fmaf(p, w, -0.0076224613f);
        p = fmaf(p, w, 0.00943887047f);
        p = fmaf(p, w, 1.00167406f);
        p = fmaf(p, w, 2.83297682f);
    }
    float n = 1.41421356f * (p * u);  // sqrt(2) * erfinv(u)
    return n * 8.0f;
}

// ---------------- kernels ----------------
// Probe whether edge indices are int64: odd 32-bit words all zero <=> int64.
__global__ void detect_kernel(const unsigned int* __restrict__ rows_words) {
    __shared__ unsigned int acc;
    if (threadIdx.x == 0) acc = 0u;
    __syncthreads();
    unsigned int v = rows_words[2 * threadIdx.x + 1];
    if (v) atomicOr(&acc, 1u);
    __syncthreads();
    if (threadIdx.x == 0) g_is64 = (acc == 0u) ? 1 : 0;
}

__global__ void zero_kernel(int which) {
    float4* p; int n4;
    if (which == 0) { p = (float4*)g_s;   n4 = NCONSTS / 4; }
    else if (which == 1) { p = (float4*)g_c2v; n4 = NVARS * F / 4; }
    else { p = (float4*)g_v2c; n4 = NCONSTS * F / 4; }
    float4 z = make_float4(0.f, 0.f, 0.f, 0.f);
    for (int i = blockIdx.x * blockDim.x + threadIdx.x; i < n4; i += gridDim.x * blockDim.x)
        p[i] = z;
}

__global__ void prep_kernel(const float* __restrict__ Wc, const float* __restrict__ Wv) {
    int f = threadIdx.x;
    if (f < F) {
        float s1 = 0.f, s2 = 0.f;
        #pragma unroll
        for (int j = 0; j < F; j++) {
            s1 += Wc[(F + j) * F + f];  // second half of Wc
            s2 += Wv[j * F + f];        // first half of Wv (ones input)
        }
        g_wsum[f] = s1;
        g_w1[f] = s2;
    }
}

__global__ void seg_sum_scalar(const void* __restrict__ cols,
                               const float* __restrict__ vals, int n) {
    int e = blockIdx.x * blockDim.x + threadIdx.x;
    int is64 = g_is64;
    if (e < n) atomicAdd(&g_s[fetch_idx(cols, e, is64)], __ldg(vals + e));
}

__global__ void __launch_bounds__(256) constraints_pass1(const float* __restrict__ bc) {
    int c = blockIdx.x * blockDim.x + threadIdx.x;
    if (c >= NCONSTS) return;
    float s = g_s[c];
    float o[F];
    #pragma unroll
    for (int f = 0; f < F; f++)
        o[f] = fmaxf(fmaf(s, g_wsum[f], __ldg(bc + f)), 0.f);
    float4* op = (float4*)g_constraints + (size_t)c * 4;
    op[0] = make_float4(o[0], o[1], o[2], o[3]);
    op[1] = make_float4(o[4], o[5], o[6], o[7]);
    op[2] = make_float4(o[8], o[9], o[10], o[11]);
    op[3] = make_float4(o[12], o[13], o[14], o[15]);
}

// mode 0/2: gather g_constraints, scatter g_c2v.  mode 1: gather g_vars, scatter g_v2c.
__global__ void __launch_bounds__(256) scatter_vec(const void* __restrict__ gidx,
                                                   const void* __restrict__ sidx,
                                                   const float* __restrict__ vals,
                                                   int n, int mode) {
    const float* src = (mode == 1) ? g_vars : g_constraints;
    float* dst = (mode == 1) ? g_v2c : g_c2v;
    int t = blockIdx.x * blockDim.x + threadIdx.x;
    int e = t >> 2, q = t & 3;
    if (e >= n) return;
    int is64 = g_is64;
    int g = fetch_idx(gidx, e, is64);
    int s = fetch_idx(sidx, e, is64);
    float v = __ldg(vals + e);
    float4 x = __ldg((const float4*)src + (size_t)g * 4 + q);
    float* d = dst + (size_t)s * F + q * 4;   // 16B-aligned
    asm volatile("red.global.add.v4.f32 [%0], {%1, %2, %3, %4};"
                 :: "l"(d), "f"(v * x.x), "f"(v * x.y), "f"(v * x.z), "f"(v * x.w)
                 : "memory");
}

__global__ void __launch_bounds__(256) vars_pass1(const float* __restrict__ Wv,
                                                  const float* __restrict__ bv) {
    __shared__ float sW[F * F];
    __shared__ float sb[F];
    int tid = threadIdx.x;
    if (tid < F * F) sW[tid] = Wv[F * F + tid];  // second half of Wv
    if (tid < F) sb[tid] = g_w1[tid] + __ldg(bv + tid);
    __syncthreads();
    int v = blockIdx.x * blockDim.x + tid;
    if (v >= NVARS) return;
    const float4* rp = (const float4*)g_c2v + (size_t)v * 4;
    float4 t0 = rp[0], t1 = rp[1], t2 = rp[2], t3 = rp[3];
    float x[F] = {t0.x, t0.y, t0.z, t0.w, t1.x, t1.y, t1.z, t1.w,
                  t2.x, t2.y, t2.z, t2.w, t3.x, t3.y, t3.z, t3.w};
    float acc[F];
    #pragma unroll
    for (int f = 0; f < F; f++) acc[f] = sb[f];
    #pragma unroll
    for (int j = 0; j < F; j++) {
        float xv = x[j];
        #pragma unroll
        for (int f = 0; f < F; f++) acc[f] = fmaf(xv, sW[j * F + f], acc[f]);
    }
    float4* op = (float4*)g_vars + (size_t)v * 4;
    op[0] = make_float4(fmaxf(acc[0],0.f), fmaxf(acc[1],0.f), fmaxf(acc[2],0.f), fmaxf(acc[3],0.f));
    op[1] = make_float4(fmaxf(acc[4],0.f), fmaxf(acc[5],0.f), fmaxf(acc[6],0.f), fmaxf(acc[7],0.f));
    op[2] = make_float4(fmaxf(acc[8],0.f), fmaxf(acc[9],0.f), fmaxf(acc[10],0.f), fmaxf(acc[11],0.f));
    op[3] = make_float4(fmaxf(acc[12],0.f), fmaxf(acc[13],0.f), fmaxf(acc[14],0.f), fmaxf(acc[15],0.f));
}

__global__ void __launch_bounds__(256) constraints_pass2(const float* __restrict__ Wc,
                                                         const float* __restrict__ bc) {
    __shared__ float sW[2 * F * F];
    __shared__ float sb[F];
    int tid = threadIdx.x;
    sW[tid] = Wc[tid];
    sW[256 + tid] = Wc[256 + tid];
    if (tid < F) sb[tid] = __ldg(bc + tid);
    __syncthreads();
    int c = blockIdx.x * blockDim.x + tid;
    if (c >= NCONSTS) return;
    const float4* cp = (const float4*)g_constraints + (size_t)c * 4;
    const float4* vp = (const float4*)g_v2c + (size_t)c * 4;
    float x[2 * F];
    {
        float4 a0 = cp[0], a1 = cp[1], a2 = cp[2], a3 = cp[3];
        float4 b0 = vp[0], b1 = vp[1], b2 = vp[2], b3 = vp[3];
        x[0]=a0.x; x[1]=a0.y; x[2]=a0.z; x[3]=a0.w; x[4]=a1.x; x[5]=a1.y; x[6]=a1.z; x[7]=a1.w;
        x[8]=a2.x; x[9]=a2.y; x[10]=a2.z; x[11]=a2.w; x[12]=a3.x; x[13]=a3.y; x[14]=a3.z; x[15]=a3.w;
        x[16]=b0.x; x[17]=b0.y; x[18]=b0.z; x[19]=b0.w; x[20]=b1.x; x[21]=b1.y; x[22]=b1.z; x[23]=b1.w;
        x[24]=b2.x; x[25]=b2.y; x[26]=b2.z; x[27]=b2.w; x[28]=b3.x; x[29]=b3.y; x[30]=b3.z; x[31]=b3.w;
    }
    float acc[F];
    #pragma unroll
    for (int f = 0; f < F; f++) acc[f] = sb[f];
    #pragma unroll
    for (int j = 0; j < 2 * F; j++) {
        float xv = x[j];
        #pragma unroll
        for (int f = 0; f < F; f++) acc[f] = fmaf(xv, sW[j * F + f], acc[f]);
    }
    float4* op = (float4*)g_constraints + (size_t)c * 4;
    op[0] = make_float4(fmaxf(acc[0],0.f), fmaxf(acc[1],0.f), fmaxf(acc[2],0.f), fmaxf(acc[3],0.f));
    op[1] = make_float4(fmaxf(acc[4],0.f), fmaxf(acc[5],0.f), fmaxf(acc[6],0.f), fmaxf(acc[7],0.f));
    op[2] = make_float4(fmaxf(acc[8],0.f), fmaxf(acc[9],0.f), fmaxf(acc[10],0.f), fmaxf(acc[11],0.f));
    op[3] = make_float4(fmaxf(acc[12],0.f), fmaxf(acc[13],0.f), fmaxf(acc[14],0.f), fmaxf(acc[15],0.f));
}

__global__ void __launch_bounds__(256) final_kernel(const float* __restrict__ Wv,
                                                    const float* __restrict__ bv,
                                                    const float* __restrict__ Wo,
                                                    const float* __restrict__ bo,
                                                    const float* __restrict__ Wo2,
                                                    const float* __restrict__ bo2,
                                                    float* __restrict__ out) {
    __shared__ float sWv[2 * F * F];
    __shared__ float sWo[F * F];
    __shared__ float sWo2[F], sbv[F], sbo[F];
    __shared__ float sbo2;
    int tid = threadIdx.x;
    sWv[tid] = Wv[tid];
    sWv[256 + tid] = Wv[256 + tid];
    sWo[tid] = Wo[tid];
    if (tid < F) { sWo2[tid] = Wo2[tid]; sbv[tid] = bv[tid]; sbo[tid] = bo[tid]; }
    if (tid == 0) sbo2 = bo2[0];
    __syncthreads();
    int v = blockIdx.x * blockDim.x + tid;
    if (v >= NVARS) return;
    const float4* ap = (const float4*)g_vars + (size_t)v * 4;
    const float4* bp = (const float4*)g_c2v + (size_t)v * 4;
    float x[2 * F];
    {
        float4 a0 = ap[0], a1 = ap[1], a2 = ap[2], a3 = ap[3];
        float4 b0 = bp[0], b1 = bp[1], b2 = bp[2], b3 = bp[3];
        x[0]=a0.x; x[1]=a0.y; x[2]=a0.z; x[3]=a0.w; x[4]=a1.x; x[5]=a1.y; x[6]=a1.z; x[7]=a1.w;
        x[8]=a2.x; x[9]=a2.y; x[10]=a2.z; x[11]=a2.w; x[12]=a3.x; x[13]=a3.y; x[14]=a3.z; x[15]=a3.w;
        x[16]=b0.x; x[17]=b0.y; x[18]=b0.z; x[19]=b0.w; x[20]=b1.x; x[21]=b1.y; x[22]=b1.z; x[23]=b1.w;
        x[24]=b2.x; x[25]=b2.y; x[26]=b2.z; x[27]=b2.w; x[28]=b3.x; x[29]=b3.y; x[30]=b3.z; x[31]=b3.w;
    }
    // variables (pass 2)
    float var[F];
    #pragma unroll
    for (int f = 0; f < F; f++) var[f] = sbv[f];
    #pragma unroll
    for (int j = 0; j < 2 * F; j++) {
        float xv = x[j];
        #pragma unroll
        for (int f = 0; f < F; f++) var[f] = fmaf(xv, sWv[j * F + f], var[f]);
    }
    #pragma unroll
    for (int f = 0; f < F; f++) var[f] = fmaxf(var[f], 0.f);
    // h = relu(var @ Wo + bo)
    float h[F];
    #pragma unroll
    for (int f = 0; f < F; f++) h[f] = sbo[f];
    #pragma unroll
    for (int j = 0; j < F; j++) {
        float xv = var[j];
        #pragma unroll
        for (int f = 0; f < F; f++) h[f] = fmaf(xv, sWo[j * F + f], h[f]);
    }
    float a = sbo2;
    #pragma unroll
    for (int f = 0; f < F; f++) a = fmaf(fmaxf(h[f], 0.f), sWo2[f], a);
    float t = a + jax_noise((unsigned int)v);
    out[v] = 1.0f / (1.0f + expf(-t));
}

// ---------------- launch ----------------
extern "C" void kernel_launch(void* const* d_in, const int* in_sizes, int n_in,
                              void* d_out, int out_size) {
    const void*  edge_rows = d_in[0];
    const void*  edge_cols = d_in[1];
    const float* edge_vals = (const float*)d_in[2];
    // d_in[3] = conditions_values (unused by reference)
    const float* Wc  = (const float*)d_in[4];
    const float* bc  = (const float*)d_in[5];
    const float* Wv  = (const float*)d_in[6];
    const float* bv  = (const float*)d_in[7];
    const float* Wo  = (const float*)d_in[8];
    const float* bo  = (const float*)d_in[9];
    const float* Wo2 = (const float*)d_in[10];
    const float* bo2 = (const float*)d_in[11];
    float* out = (float*)d_out;
    int nE = in_sizes[0];

    const int TB = 256;
    int gE  = (nE + TB - 1) / TB;            // 1 thread / edge
    int gE4 = (4 * nE + TB - 1) / TB;        // 4 threads / edge (int-safe: 32M < 2^31)
    int gC  = (NCONSTS + TB - 1) / TB;
    int gV  = (NVARS + TB - 1) / TB;

    detect_kernel<<<1, 1024>>>((const unsigned int*)edge_rows);
    prep_kernel<<<1, 32>>>(Wc, Wv);
    zero_kernel<<<2048, TB>>>(0);                                    // g_s = 0
    seg_sum_scalar<<<gE, TB>>>(edge_cols, edge_vals, nE);            // pass-1 v2c (scalar)
    constraints_pass1<<<gC, TB>>>(bc);                               // constraints (pass 1)
    zero_kernel<<<8192, TB>>>(1);                                    // g_c2v = 0
    scatter_vec<<<gE4, TB>>>(edge_cols, edge_rows, edge_vals, nE, 0);// pass-1 c2v
    vars_pass1<<<gV, TB>>>(Wv, bv);                                  // variables (pass 1)
    zero_kernel<<<8192, TB>>>(2);                                    // g_v2c = 0
    scatter_vec<<<gE4, TB>>>(edge_rows, edge_cols, edge_vals, nE, 1);// pass-2 v2c
    constraints_pass2<<<gC, TB>>>(Wc, bc);                           // constraints (pass 2)
    zero_kernel<<<8192, TB>>>(1);                                    // g_c2v = 0
    scatter_vec<<<gE4, TB>>>(edge_cols, edge_rows, edge_vals, nE, 2);// pass-2 c2v
    final_kernel<<<gV, TB>>>(Wv, bv, Wo, bo, Wo2, bo2, out);         // fused vars2+head+noise
}